// round 14
// baseline (speedup 1.0000x reference)
#include <cuda_runtime.h>
#include <cstdint>
#include <cstddef>

#define NN 8192
#define RWD 10
#define HD1 100
#define HD2 100
#define NB_SEG 256

#define MSPLIT 16
#define MW 64                       // m-window per stage
#define ROWSB 128                   // rows per block (32 lanes x 4)
#define ITERS ((NN / MSPLIT) / MW)  // 8
#define HOP_TILE_BYTES (ROWSB * MW * 4)   // 32768
#define X_TILE_BYTES (MW * RWD * 4)       // 2560
// 3 ring buffers + 16B control word
#define SMEM_A_BYTES (3 * (HOP_TILE_BYTES + X_TILE_BYTES) + 16)  // 106000

#define NBLK 304                         // 2 blocks/SM x 152 SMs
#define NWU  (3 * MSPLIT * (NN / ROWSB)) // 3072 work units
#define WMOD (NWU + NBLK)                // tickets consumed per launch

typedef unsigned long long u64;

// ---------------- scratch (static device arrays; no allocation) ----------------
__device__ float g_part[3 * MSPLIT * NN * RWD];  // per-m-split partials of hopX
__device__ float g_nodeout[NN * HD2];            // per-node summed MLP output
__device__ int   g_ctr;                          // persistent ticket counter

// ---------------- helpers ----------------
__device__ __forceinline__ void fma2(u64 &acc, u64 a, u64 b) {
    asm("fma.rn.f32x2 %0, %1, %2, %0;" : "+l"(acc) : "l"(a), "l"(b));
}
__device__ __forceinline__ u64 pack2(float x, float y) {
    u64 r; asm("mov.b64 %0, {%1, %2};" : "=l"(r) : "f"(x), "f"(y)); return r;
}
__device__ __forceinline__ float2 unpack2(u64 v) {
    float2 r; asm("mov.b64 {%0, %1}, %2;" : "=f"(r.x), "=f"(r.y) : "l"(v)); return r;
}
__device__ __forceinline__ void cp_async16(uint32_t dst, const void* src) {
    asm volatile("cp.async.cg.shared.global [%0], [%1], 16;" :: "r"(dst), "l"(src));
}
__device__ __forceinline__ void cp_commit() { asm volatile("cp.async.commit_group;"); }
template<int N> __device__ __forceinline__ void cp_wait() {
    asm volatile("cp.async.wait_group %0;" :: "n"(N));
}

// =====================================================================
// Kernel A: persistent-CTA hop GEMV. 304 blocks; work units (k, rg, sp)
// grabbed from a ticket counter; cp.async ring (3 bufs, depth-2) runs
// continuously ACROSS work units. Per-wu reduction uses the just-freed
// ring buffer in two 20KB half-row passes.
// =====================================================================
extern "C" __global__ void __launch_bounds__(256, 2)
hop_gemv_kernel(const float* __restrict__ hop0, const float* __restrict__ hop1,
                const float* __restrict__ hop2, const float* __restrict__ X)
{
    extern __shared__ char smem[];
    char* hop_s = smem;                                   // 3 x 32KB
    char* x_s   = smem + 3 * HOP_TILE_BYTES;              // 3 x 2.5KB
    int*  ctl   = (int*)(smem + 3 * (HOP_TILE_BYTES + X_TILE_BYTES));

    const int t = threadIdx.x;
    const int w = t >> 5, l = t & 31;
    const int tr = t >> 4;                    // 0..15
    const int tc = t & 15;                    // float4 column
    const int slotS = tc ^ (tr & 7);
    const uint32_t hdst0 = (uint32_t)__cvta_generic_to_shared(hop_s)
                         + (uint32_t)((tr * 16 + slotS) * 16);
    const uint32_t xdst0 = (uint32_t)__cvta_generic_to_shared(x_s) + (uint32_t)(t * 16);

    auto mkg = [&](int wu) -> const char* {
        int k = wu >> 10, rem = wu & 1023, rg = rem >> 4, sp = rem & 15;
        const float* hp = (k == 0) ? hop0 : (k == 1) ? hop1 : hop2;
        return (const char*)(hp + (size_t)(rg * ROWSB + tr) * NN
                                + sp * (NN / MSPLIT) + tc * 4);
    };
    auto mkx = [&](int wu) -> const char* {
        int sp = wu & 15;
        return (const char*)(X + (size_t)(sp * (NN / MSPLIT)) * RWD);
    };

    auto stage = [&](const char* gb, const char* xb, int it, int buf) {
        const char* gs = gb + (size_t)it * (MW * 4);
        uint32_t hd = hdst0 + buf * HOP_TILE_BYTES;
        #pragma unroll
        for (int i = 0; i < 8; i++)
            cp_async16(hd + i * 4096, gs + (size_t)i * (16 * NN * 4));
        if (t < 160)
            cp_async16(xdst0 + buf * X_TILE_BYTES, xb + it * X_TILE_BYTES + t * 16);
        cp_commit();
    };

    u64 acc[4][5];
    #pragma unroll
    for (int g = 0; g < 4; g++)
        #pragma unroll
        for (int p = 0; p < 5; p++) acc[g][p] = 0ull;

    // initial grab
    if (t == 0) {
        int v = atomicAdd(&g_ctr, 1) % WMOD;
        ctl[0] = (v < NWU) ? v : -1;
    }
    __syncthreads();
    int cur = ctl[0];
    const char *gb_cur = nullptr, *xb_cur = nullptr;
    int ib = 0, cb = 0, issued = 0, computed = 0;
    if (cur >= 0) {
        gb_cur = mkg(cur); xb_cur = mkx(cur);
        stage(gb_cur, xb_cur, 0, 0);
        stage(gb_cur, xb_cur, 1, 1);
        ib = 2; issued = 2;
    }

    while (cur >= 0) {
        int nxt = -1;
        int freebuf = 0;
        #pragma unroll 1
        for (int it = 0; it < ITERS; it++) {
            __syncthreads();                    // consumed buffer free / epi done
            if (it == 5 && t == 0) {            // grab next wu (visible at it==6)
                int v = atomicAdd(&g_ctr, 1) % WMOD;
                ctl[0] = (v < NWU) ? v : -1;
            }
            if (it + 2 < ITERS) {
                stage(gb_cur, xb_cur, it + 2, ib);
                ib = (ib == 2) ? 0 : ib + 1; issued++;
            } else {
                if (it == 6) nxt = ctl[0];
                if (nxt >= 0) {                  // prefetch next wu's stages 0,1
                    stage(mkg(nxt), mkx(nxt), it - 6, ib);
                    ib = (ib == 2) ? 0 : ib + 1; issued++;
                }
            }
            int gap = issued - computed - 1;
            if (gap >= 2)      cp_wait<2>();
            else if (gap == 1) cp_wait<1>();
            else               cp_wait<0>();
            __syncthreads();                    // buffer cb visible to all warps

            const float4* hb = (const float4*)(hop_s + cb * HOP_TILE_BYTES);
            const u64*    xb = (const u64*)(x_s + cb * X_TILE_BYTES);

            #pragma unroll
            for (int q = 0; q < 2; q++) {
                const int c4   = (w << 1) + q;          // 0..15
                const int slot = c4 ^ (l & 7);
                float4 h4[4];
                #pragma unroll
                for (int g = 0; g < 4; g++)
                    h4[g] = hb[((l + (g << 5)) << 4) + slot];
                const u64* xp = xb + c4 * 20;
                #pragma unroll
                for (int j = 0; j < 4; j++) {
                    const float* hv0 = (const float*)&h4[0];
                    const float* hv1 = (const float*)&h4[1];
                    const float* hv2 = (const float*)&h4[2];
                    const float* hv3 = (const float*)&h4[3];
                    u64 A0 = pack2(hv0[j], hv0[j]);
                    u64 A1 = pack2(hv1[j], hv1[j]);
                    u64 A2 = pack2(hv2[j], hv2[j]);
                    u64 A3 = pack2(hv3[j], hv3[j]);
                    #pragma unroll
                    for (int p = 0; p < 5; p++) {
                        u64 xv = xp[j * 5 + p];
                        fma2(acc[0][p], A0, xv);
                        fma2(acc[1][p], A1, xv);
                        fma2(acc[2][p], A2, xv);
                        fma2(acc[3][p], A3, xv);
                    }
                }
            }
            computed++; freebuf = cb; cb = (cb == 2) ? 0 : cb + 1;
        }

        // ---- epilogue: reduce + store this wu (freebuf is idle in the ring) ----
        {
            int k = cur >> 10, rem = cur & 1023, rg = rem >> 4, sp = rem & 15;
            float* gout = g_part + ((size_t)(k * MSPLIT + sp) * NN + rg * ROWSB) * RWD;
            float* red = (float*)(hop_s + freebuf * HOP_TILE_BYTES);  // 20KB used
            __syncthreads();        // all warps done reading freebuf
            #pragma unroll
            for (int half = 0; half < 2; half++) {
                #pragma unroll
                for (int g2 = 0; g2 < 2; g2++) {
                    int gg = half * 2 + g2;
                    int rrow = l + (g2 << 5);            // 0..63 local row
                    #pragma unroll
                    for (int p = 0; p < 5; p++) {
                        float2 v = unpack2(acc[gg][p]);
                        red[(w * 64 + rrow) * 10 + 2 * p]     = v.x;
                        red[(w * 64 + rrow) * 10 + 2 * p + 1] = v.y;
                        acc[gg][p] = 0ull;               // reset for next wu
                    }
                }
                __syncthreads();
                for (int f = t; f < 640; f += 256) {
                    int row = f / 10, d = f % 10;
                    float s = 0.f;
                    #pragma unroll
                    for (int ww = 0; ww < 8; ww++) s += red[(ww * 64 + row) * 10 + d];
                    gout[(size_t)(half * 64 + row) * 10 + d] = s;
                }
                __syncthreads();
            }
        }
        cur = nxt;
        if (cur >= 0) { gb_cur = mkg(cur); xb_cur = mkx(cur); }
    }
}

// =====================================================================
// Kernel B: node-parallel MLP, 256 blocks x 32 nodes. (R12 version, keep)
// =====================================================================
#define W2S_BYTES 40000
#define SMEM_H_OFF   80000            // hsm: [32][100] float = 12800B
#define SMEM_INP_OFF 92800            // inp: 1280B
#define SMEM_B2_OFF  94080            // b2s: 400B
#define SMEM_MLP_BYTES 94592

extern "C" __global__ void __launch_bounds__(256, 2)
mlp_kernel(const float* __restrict__ X, const float* __restrict__ W1,
           const float* __restrict__ b1, const float* __restrict__ W2,
           const float* __restrict__ b2)
{
    extern __shared__ char smemb[];
    float* hsm  = (float*)(smemb + SMEM_H_OFF);   // [32][100] h (plain)
    float* inp  = (float*)(smemb + SMEM_INP_OFF); // [320]
    float* b2s  = (float*)(smemb + SMEM_B2_OFF);  // [100]

    const int t = threadIdx.x;
    const int w = t >> 5, l = t & 31;
    const int node0 = blockIdx.x * 32;

    const uint32_t w2base = (uint32_t)__cvta_generic_to_shared(smemb);

    auto stageW2 = [&](int buf, int k) {
        const float4* src = (const float4*)(W2 + k * 10000);  // 2500 x 16B
        uint32_t dst = w2base + buf * W2S_BYTES;
        #pragma unroll
        for (int i = 0; i < 9; i++)
            cp_async16(dst + (i * 256 + t) * 16, src + i * 256 + t);
        if (t < 196)
            cp_async16(dst + (2304 + t) * 16, src + 2304 + t);
        cp_commit();
    };

    if (t < 100) b2s[t] = b2[t] + b2[100 + t] + b2[200 + t] + b2[300 + t];

    stageW2(0, 0);
    stageW2(1, 1);

    u64 acc[8][2];
    #pragma unroll
    for (int nn = 0; nn < 8; nn++) { acc[nn][0] = 0ull; acc[nn][1] = 0ull; }

    #pragma unroll 1
    for (int k = 0; k < 4; k++) {
        if (k == 0) {
            for (int f = t; f < 320; f += 256) inp[f] = X[(size_t)node0 * RWD + f];
        } else {
            const float* base = g_part + ((size_t)(k - 1) * MSPLIT * NN + node0) * RWD;
            for (int f = t; f < 320; f += 256) {
                float s = 0.f;
                #pragma unroll
                for (int sp = 0; sp < MSPLIT; sp++)
                    s += base[(size_t)sp * NN * RWD + f];
                inp[f] = s;
            }
        }
        if (k < 3) cp_wait<1>(); else cp_wait<0>();
        __syncthreads();   // weights(k) + inp visible; hsm free

        // ---- phase 1: warp = 4 nodes, lane<25 = j-quad ----
        if (l < 25) {
            const float* w1k = W1 + k * 1000;
            ulonglong2 w1p[10];
            #pragma unroll
            for (int r = 0; r < 10; r++)
                w1p[r] = *(const ulonglong2*)(w1k + r * 100 + 4 * l);
            float4 b1q = *(const float4*)(b1 + k * 100 + 4 * l);
            u64 binit0 = pack2(b1q.x, b1q.y), binit1 = pack2(b1q.z, b1q.w);
            #pragma unroll
            for (int nn = 0; nn < 4; nn++) {
                const int row = w * 4 + nn;
                u64 s0 = binit0, s1 = binit1;
                #pragma unroll
                for (int r = 0; r < 10; r++) {
                    float xv = inp[row * 10 + r];   // broadcast
                    u64 xp2 = pack2(xv, xv);
                    fma2(s0, xp2, w1p[r].x);
                    fma2(s1, xp2, w1p[r].y);
                }
                float2 a = unpack2(s0), bvv = unpack2(s1);
                float4 hq = { fmaxf(a.x, 0.f), fmaxf(a.y, 0.f),
                              fmaxf(bvv.x, 0.f), fmaxf(bvv.y, 0.f) };
                *(float4*)&hsm[row * 100 + 4 * l] = hq;   // plain, 16B
            }
        }
        __syncthreads();

        // ---- phase 2: warps 0-3, 8 nodes each; lane<25 = o-quad ----
        if (w < 4 && l < 25) {
            const float* w2f = (const float*)(smemb + (k & 1) * W2S_BYTES);
            #pragma unroll 5
            for (int d4 = 0; d4 < 25; d4++) {
                u64 wq[4][2];
                #pragma unroll
                for (int j = 0; j < 4; j++) {
                    ulonglong2 ww = *(const ulonglong2*)&w2f[(4 * d4 + j) * 100 + 4 * l];
                    wq[j][0] = ww.x; wq[j][1] = ww.y;
                }
                #pragma unroll
                for (int nn = 0; nn < 8; nn++) {
                    const int row = w * 8 + nn;
                    float4 hq = *(const float4*)&hsm[row * 100 + 4 * d4];  // broadcast
                    u64 h0 = pack2(hq.x, hq.x);
                    u64 h1 = pack2(hq.y, hq.y);
                    u64 h2 = pack2(hq.z, hq.z);
                    u64 h3 = pack2(hq.w, hq.w);
                    fma2(acc[nn][0], h0, wq[0][0]); fma2(acc[nn][1], h0, wq[0][1]);
                    fma2(acc[nn][0], h1, wq[1][0]); fma2(acc[nn][1], h1, wq[1][1]);
                    fma2(acc[nn][0], h2, wq[2][0]); fma2(acc[nn][1], h2, wq[2][1]);
                    fma2(acc[nn][0], h3, wq[3][0]); fma2(acc[nn][1], h3, wq[3][1]);
                }
            }
        }
        __syncthreads();   // w2 buffer (k&1) free for restage
        if (k + 2 < 4) stageW2(k & 1, k + 2);
    }

    // ---- output: node_out = acc + sum_k b2 ----
    if (w < 4 && l < 25) {
        float4 bv = *(const float4*)&b2s[4 * l];
        #pragma unroll
        for (int nn = 0; nn < 8; nn++) {
            int n = node0 + w * 8 + nn;
            float2 a0 = unpack2(acc[nn][0]);
            float2 a1 = unpack2(acc[nn][1]);
            float4 o4 = { a0.x + bv.x, a0.y + bv.y, a1.x + bv.z, a1.y + bv.w };
            *(float4*)&g_nodeout[(size_t)n * 100 + 4 * l] = o4;
        }
    }
}

// =====================================================================
// Kernel C: deterministic segment sum; 4 node-chunks per segment summed
// in fixed order (chunk 0..3) -> deterministic, 4x more parallel.
// =====================================================================
__device__ __forceinline__ int lbound(const int* a, int n, int v) {
    int lo = 0, hi = n;
    while (lo < hi) { int mid = (lo + hi) >> 1; if (a[mid] < v) lo = mid + 1; else hi = mid; }
    return lo;
}

extern "C" __global__ void segpool_kernel(const int* __restrict__ bidx,
                                          float* __restrict__ out)
{
    __shared__ float partial[4][100];
    const int b = blockIdx.x;
    const int lo = lbound(bidx, NN, b);
    const int hi = lbound(bidx, NN, b + 1);
    const int t = threadIdx.x;            // 512
    const int c = t >> 7, oo = t & 127;
    if (oo < 100) {
        float s = 0.f;
        for (int n = lo + c; n < hi; n += 4)
            s += g_nodeout[(size_t)n * 100 + oo];
        partial[c][oo] = s;
    }
    __syncthreads();
    if (t < 100)
        out[b * 100 + t] = partial[0][t] + partial[1][t] + partial[2][t] + partial[3][t];
}

// =====================================================================
extern "C" void kernel_launch(void* const* d_in, const int* in_sizes, int n_in,
                              void* d_out, int out_size)
{
    const float* X    = (const float*)d_in[0];   // walk_feats (8192,10)
    const float* hop1 = (const float*)d_in[1];
    const float* hop2 = (const float*)d_in[2];
    const float* hop3 = (const float*)d_in[3];
    const int*   bidx = (const int*)d_in[4];
    const float* W1   = (const float*)d_in[5];   // (4,10,100)
    const float* b1   = (const float*)d_in[6];   // (4,100)
    const float* W2   = (const float*)d_in[7];   // (4,100,100)
    const float* b2   = (const float*)d_in[8];   // (4,100)
    float* out = (float*)d_out;                  // (256,100)

    (void)in_sizes; (void)n_in; (void)out_size;

    cudaFuncSetAttribute(hop_gemv_kernel, cudaFuncAttributeMaxDynamicSharedMemorySize, SMEM_A_BYTES);
    cudaFuncSetAttribute(mlp_kernel,      cudaFuncAttributeMaxDynamicSharedMemorySize, SMEM_MLP_BYTES);

    hop_gemv_kernel<<<NBLK, 256, SMEM_A_BYTES>>>(hop1, hop2, hop3, X);
    mlp_kernel<<<256, 256, SMEM_MLP_BYTES>>>(X, W1, b1, W2, b2);
    segpool_kernel<<<NB_SEG, 512>>>(bidx, out);
}

// round 16
// speedup vs baseline: 1.0027x; 1.0027x over previous
#include <cuda_runtime.h>
#include <cstdint>
#include <cstddef>

#define NN 8192
#define RWD 10
#define HD1 100
#define HD2 100
#define NB_SEG 256

#define MSPLIT 16
#define MW 64                       // m-window per stage
#define ROWSB 128                   // rows per block (32 lanes x 4)
#define ITERS ((NN / MSPLIT) / MW)  // 8
#define HOP_TILE_BYTES (ROWSB * MW * 4)   // 32768
#define X_TILE_BYTES (MW * RWD * 4)       // 2560
// triple-buffered: depth-2 prefetch (proven best R8/R10/R12)
#define SMEM_A_BYTES (3 * (HOP_TILE_BYTES + X_TILE_BYTES))  // 105984 -> 2 blocks/SM

typedef unsigned long long u64;

// ---------------- scratch (static device arrays; no allocation) ----------------
__device__ float g_part[3 * MSPLIT * NN * RWD];  // per-m-split partials of hopX
__device__ float g_hopX[3 * NN * RWD];           // collapsed hopX (presum output)
__device__ float g_nodeout[NN * HD2];            // per-node summed MLP output

// ---------------- helpers ----------------
__device__ __forceinline__ void fma2(u64 &acc, u64 a, u64 b) {
    asm("fma.rn.f32x2 %0, %1, %2, %0;" : "+l"(acc) : "l"(a), "l"(b));
}
__device__ __forceinline__ u64 pack2(float x, float y) {
    u64 r; asm("mov.b64 %0, {%1, %2};" : "=l"(r) : "f"(x), "f"(y)); return r;
}
__device__ __forceinline__ float2 unpack2(u64 v) {
    float2 r; asm("mov.b64 {%0, %1}, %2;" : "=f"(r.x), "=f"(r.y) : "l"(v)); return r;
}
__device__ __forceinline__ void cp_async16(uint32_t dst, const void* src) {
    asm volatile("cp.async.cg.shared.global [%0], [%1], 16;" :: "r"(dst), "l"(src));
}
__device__ __forceinline__ void cp_commit() { asm volatile("cp.async.commit_group;"); }
template<int N> __device__ __forceinline__ void cp_wait() {
    asm volatile("cp.async.wait_group %0;" :: "n"(N));
}

// =====================================================================
// Kernel A: partial hopX over this block's m-range (512 m of one hop).
// Exact R12 configuration (best measured: 126.6us, 82% DRAM).
// =====================================================================
extern "C" __global__ void __launch_bounds__(256, 2)
hop_gemv_kernel(const float* __restrict__ hop0, const float* __restrict__ hop1,
                const float* __restrict__ hop2, const float* __restrict__ X)
{
    extern __shared__ char smem[];
    char* hop_s = smem;                                   // 3 x 32KB
    char* x_s   = smem + 3 * HOP_TILE_BYTES;              // 3 x 2.5KB

    const int b   = blockIdx.x;                  // 3072 blocks
    const int k   = b >> 10;                     // 0..2
    const int rem = b & 1023;
    const int rg  = rem >> 4;                    // row group 0..63
    const int sp  = rem & 15;                    // m split 0..15
    const int row0   = rg * ROWSB;
    const int m_base = sp * (NN / MSPLIT);
    const float* hop = (k == 0) ? hop0 : (k == 1) ? hop1 : hop2;

    const int t = threadIdx.x;
    const int w = t >> 5, l = t & 31;

    const int tr = t >> 4;                    // 0..15
    const int tc = t & 15;                    // float4 column 0..15
    const int slotS = tc ^ (tr & 7);
    const char* gsrc0 = (const char*)(hop + (size_t)(row0 + tr) * NN + m_base + tc * 4);
    const uint32_t hdst0 = (uint32_t)__cvta_generic_to_shared(hop_s)
                         + (uint32_t)((tr * 16 + slotS) * 16);
    const char* xsrc0 = (const char*)(X + (size_t)m_base * RWD);
    const uint32_t xdst0 = (uint32_t)__cvta_generic_to_shared(x_s) + (uint32_t)(t * 16);

    auto stage = [&](int buf, int it) {
        const char* gs = gsrc0 + (size_t)it * (MW * 4);
        uint32_t hd = hdst0 + buf * HOP_TILE_BYTES;
        #pragma unroll
        for (int i = 0; i < 8; i++)
            cp_async16(hd + i * 4096, gs + (size_t)i * (16 * NN * 4));
        if (t < 160)
            cp_async16(xdst0 + buf * X_TILE_BYTES, xsrc0 + (size_t)it * X_TILE_BYTES + t * 16);
        cp_commit();
    };

    u64 acc[4][5];
    #pragma unroll
    for (int g = 0; g < 4; g++)
        #pragma unroll
        for (int p = 0; p < 5; p++) acc[g][p] = 0ull;

    stage(0, 0);
    stage(1, 1);

    int bc = 2;
    #pragma unroll 1
    for (int it = 0; it < ITERS; it++) {
        __syncthreads();                    // compute(it-1) done -> buffer free
        if (it + 2 < ITERS) {
            stage(bc, it + 2);
            bc = (bc == 2) ? 0 : bc + 1;
            cp_wait<2>();
        } else if (it + 1 < ITERS) cp_wait<1>();
        else                       cp_wait<0>();
        __syncthreads();                    // buffer it visible to all warps

        const float4* hb = (const float4*)(hop_s + (it % 3) * HOP_TILE_BYTES);
        const u64*    xb = (const u64*)(x_s + (it % 3) * X_TILE_BYTES);

        #pragma unroll
        for (int q = 0; q < 2; q++) {
            const int c4   = (w << 1) + q;          // 0..15
            const int slot = c4 ^ (l & 7);
            float4 h4[4];
            #pragma unroll
            for (int g = 0; g < 4; g++)
                h4[g] = hb[((l + (g << 5)) << 4) + slot];
            const u64* xp = xb + c4 * 20;
            #pragma unroll
            for (int j = 0; j < 4; j++) {
                const float* hv0 = (const float*)&h4[0];
                const float* hv1 = (const float*)&h4[1];
                const float* hv2 = (const float*)&h4[2];
                const float* hv3 = (const float*)&h4[3];
                u64 A0 = pack2(hv0[j], hv0[j]);
                u64 A1 = pack2(hv1[j], hv1[j]);
                u64 A2 = pack2(hv2[j], hv2[j]);
                u64 A3 = pack2(hv3[j], hv3[j]);
                #pragma unroll
                for (int p = 0; p < 5; p++) {
                    u64 xv = xp[j * 5 + p];
                    fma2(acc[0][p], A0, xv);
                    fma2(acc[1][p], A1, xv);
                    fma2(acc[2][p], A2, xv);
                    fma2(acc[3][p], A3, xv);
                }
            }
        }
    }

    float* red = (float*)smem;
    __syncthreads();
    #pragma unroll
    for (int g = 0; g < 4; g++) {
        int row = l + (g << 5);
        #pragma unroll
        for (int p = 0; p < 5; p++) {
            float2 v = unpack2(acc[g][p]);
            red[(w * ROWSB + row) * RWD + 2 * p]     = v.x;
            red[(w * ROWSB + row) * RWD + 2 * p + 1] = v.y;
        }
    }
    __syncthreads();
    for (int f = t; f < ROWSB * RWD; f += 256) {
        int row = f / RWD, d = f % RWD;
        float s = 0.f;
        #pragma unroll
        for (int ww = 0; ww < 8; ww++) s += red[(ww * ROWSB + row) * RWD + d];
        g_part[((size_t)(k * MSPLIT + sp) * NN + row0 + row) * RWD + d] = s;
    }
}

// =====================================================================
// Kernel A2: collapse the 16 m-split partials into g_hopX.
// float4-vectorized, fully coalesced, MLP=16 per thread. ~3us.
// Deterministic: fixed sp order 0..15.
// =====================================================================
#define PLANE4 (NN * RWD / 4)       // 20480 float4 per k-plane

extern "C" __global__ void __launch_bounds__(256)
presum_kernel()
{
    const int idx = blockIdx.x * 256 + threadIdx.x;   // 0..61439
    const int k  = idx / PLANE4;
    const int r4 = idx - k * PLANE4;
    const float4* src = (const float4*)g_part + (size_t)(k * MSPLIT) * PLANE4 + r4;
    float4 s = src[0];
    #pragma unroll
    for (int sp = 1; sp < MSPLIT; sp++) {
        float4 v = src[(size_t)sp * PLANE4];
        s.x += v.x; s.y += v.y; s.z += v.z; s.w += v.w;
    }
    ((float4*)g_hopX)[idx] = s;
}

// =====================================================================
// Kernel B: node-parallel MLP, 256 blocks x 32 nodes.
// All 4 k-inputs loaded upfront (one coalesced LDG round, overlapped with
// the W2 cp.async prologue) -> zero global loads inside the k-loop.
// Phase 1: warp = 4 nodes, lane<25 = j-quad (register-tiled W1).
// Phase 2: warps 0-3 x 8 nodes, lane<25 = o-quad; W2 natural [d][o].
// =====================================================================
#define W2S_BYTES 40000
#define SMEM_H_OFF   80000            // hsm: [32][100] float = 12800B
#define SMEM_INP_OFF 92800            // inpAll: [4][320] = 5120B
#define SMEM_B2_OFF  97920            // b2s: 400B
#define SMEM_MLP_BYTES 98432

extern "C" __global__ void __launch_bounds__(256, 2)
mlp_kernel(const float* __restrict__ X, const float* __restrict__ W1,
           const float* __restrict__ b1, const float* __restrict__ W2,
           const float* __restrict__ b2)
{
    extern __shared__ char smemb[];
    float* hsm    = (float*)(smemb + SMEM_H_OFF);   // [32][100]
    float* inpAll = (float*)(smemb + SMEM_INP_OFF); // [4][320]
    float* b2s    = (float*)(smemb + SMEM_B2_OFF);  // [100]

    const int t = threadIdx.x;
    const int w = t >> 5, l = t & 31;
    const int node0 = blockIdx.x * 32;

    const uint32_t w2base = (uint32_t)__cvta_generic_to_shared(smemb);

    auto stageW2 = [&](int buf, int k) {
        const float4* src = (const float4*)(W2 + k * 10000);  // 2500 x 16B
        uint32_t dst = w2base + buf * W2S_BYTES;
        #pragma unroll
        for (int i = 0; i < 9; i++)
            cp_async16(dst + (i * 256 + t) * 16, src + i * 256 + t);
        if (t < 196)
            cp_async16(dst + (2304 + t) * 16, src + 2304 + t);
        cp_commit();
    };

    stageW2(0, 0);
    stageW2(1, 1);

    // upfront: all 4 k-inputs (LDG overlaps with outstanding cp.async)
    for (int f = t; f < 1280; f += 256) {
        int kk = f / 320, r = f - kk * 320;
        inpAll[f] = (kk == 0)
            ? X[(size_t)node0 * RWD + r]
            : g_hopX[(size_t)(kk - 1) * NN * RWD + (size_t)node0 * RWD + r];
    }
    if (t < 100) b2s[t] = b2[t] + b2[100 + t] + b2[200 + t] + b2[300 + t];

    u64 acc[8][2];
    #pragma unroll
    for (int nn = 0; nn < 8; nn++) { acc[nn][0] = 0ull; acc[nn][1] = 0ull; }

    #pragma unroll 1
    for (int k = 0; k < 4; k++) {
        if (k < 3) cp_wait<1>(); else cp_wait<0>();
        __syncthreads();   // weights(k) + inputs visible; hsm free

        // ---- phase 1: warp = 4 nodes, lane<25 = j-quad ----
        if (l < 25) {
            const float* w1k = W1 + k * 1000;
            const float* inp = inpAll + k * 320;
            ulonglong2 w1p[10];
            #pragma unroll
            for (int r = 0; r < 10; r++)
                w1p[r] = *(const ulonglong2*)(w1k + r * 100 + 4 * l);
            float4 b1q = *(const float4*)(b1 + k * 100 + 4 * l);
            u64 binit0 = pack2(b1q.x, b1q.y), binit1 = pack2(b1q.z, b1q.w);
            #pragma unroll
            for (int nn = 0; nn < 4; nn++) {
                const int row = w * 4 + nn;
                u64 s0 = binit0, s1 = binit1;
                #pragma unroll
                for (int r = 0; r < 10; r++) {
                    float xv = inp[row * 10 + r];   // broadcast
                    u64 xp2 = pack2(xv, xv);
                    fma2(s0, xp2, w1p[r].x);
                    fma2(s1, xp2, w1p[r].y);
                }
                float2 a = unpack2(s0), bvv = unpack2(s1);
                float4 hq = { fmaxf(a.x, 0.f), fmaxf(a.y, 0.f),
                              fmaxf(bvv.x, 0.f), fmaxf(bvv.y, 0.f) };
                *(float4*)&hsm[row * 100 + 4 * l] = hq;   // plain, 16B
            }
        }
        __syncthreads();

        // ---- phase 2: warps 0-3, 8 nodes each; lane<25 = o-quad ----
        if (w < 4 && l < 25) {
            const float* w2f = (const float*)(smemb + (k & 1) * W2S_BYTES);
            #pragma unroll 5
            for (int d4 = 0; d4 < 25; d4++) {
                u64 wq[4][2];
                #pragma unroll
                for (int j = 0; j < 4; j++) {
                    ulonglong2 ww = *(const ulonglong2*)&w2f[(4 * d4 + j) * 100 + 4 * l];
                    wq[j][0] = ww.x; wq[j][1] = ww.y;
                }
                #pragma unroll
                for (int nn = 0; nn < 8; nn++) {
                    const int row = w * 8 + nn;
                    float4 hq = *(const float4*)&hsm[row * 100 + 4 * d4];  // broadcast
                    u64 h0 = pack2(hq.x, hq.x);
                    u64 h1 = pack2(hq.y, hq.y);
                    u64 h2 = pack2(hq.z, hq.z);
                    u64 h3 = pack2(hq.w, hq.w);
                    fma2(acc[nn][0], h0, wq[0][0]); fma2(acc[nn][1], h0, wq[0][1]);
                    fma2(acc[nn][0], h1, wq[1][0]); fma2(acc[nn][1], h1, wq[1][1]);
                    fma2(acc[nn][0], h2, wq[2][0]); fma2(acc[nn][1], h2, wq[2][1]);
                    fma2(acc[nn][0], h3, wq[3][0]); fma2(acc[nn][1], h3, wq[3][1]);
                }
            }
        }
        __syncthreads();   // w2 buffer (k&1) free for restage
        if (k + 2 < 4) stageW2(k & 1, k + 2);
    }

    // ---- output: node_out = acc + sum_k b2 ----
    if (w < 4 && l < 25) {
        float4 bv = *(const float4*)&b2s[4 * l];
        #pragma unroll
        for (int nn = 0; nn < 8; nn++) {
            int n = node0 + w * 8 + nn;
            float2 a0 = unpack2(acc[nn][0]);
            float2 a1 = unpack2(acc[nn][1]);
            float4 o4 = { a0.x + bv.x, a0.y + bv.y, a1.x + bv.z, a1.y + bv.w };
            *(float4*)&g_nodeout[(size_t)n * 100 + 4 * l] = o4;
        }
    }
}

// =====================================================================
// Kernel C: deterministic segment sum via binary search on sorted batch_idx
// =====================================================================
__device__ __forceinline__ int lbound(const int* a, int n, int v) {
    int lo = 0, hi = n;
    while (lo < hi) { int mid = (lo + hi) >> 1; if (a[mid] < v) lo = mid + 1; else hi = mid; }
    return lo;
}

extern "C" __global__ void segpool_kernel(const int* __restrict__ bidx,
                                          float* __restrict__ out)
{
    const int b = blockIdx.x;
    const int lo = lbound(bidx, NN, b);
    const int hi = lbound(bidx, NN, b + 1);
    const int t = threadIdx.x;
    if (t < 100) {
        float s = 0.f;
        int n = lo;
        for (; n + 3 < hi; n += 4) {
            s += g_nodeout[(size_t)n * 100 + t];
            s += g_nodeout[(size_t)(n + 1) * 100 + t];
            s += g_nodeout[(size_t)(n + 2) * 100 + t];
            s += g_nodeout[(size_t)(n + 3) * 100 + t];
        }
        for (; n < hi; n++) s += g_nodeout[(size_t)n * 100 + t];
        out[b * 100 + t] = s;
    }
}

// =====================================================================
extern "C" void kernel_launch(void* const* d_in, const int* in_sizes, int n_in,
                              void* d_out, int out_size)
{
    const float* X    = (const float*)d_in[0];   // walk_feats (8192,10)
    const float* hop1 = (const float*)d_in[1];
    const float* hop2 = (const float*)d_in[2];
    const float* hop3 = (const float*)d_in[3];
    const int*   bidx = (const int*)d_in[4];
    const float* W1   = (const float*)d_in[5];   // (4,10,100)
    const float* b1   = (const float*)d_in[6];   // (4,100)
    const float* W2   = (const float*)d_in[7];   // (4,100,100)
    const float* b2   = (const float*)d_in[8];   // (4,100)
    float* out = (float*)d_out;                  // (256,100)

    (void)in_sizes; (void)n_in; (void)out_size;

    cudaFuncSetAttribute(hop_gemv_kernel, cudaFuncAttributeMaxDynamicSharedMemorySize, SMEM_A_BYTES);
    cudaFuncSetAttribute(mlp_kernel,      cudaFuncAttributeMaxDynamicSharedMemorySize, SMEM_MLP_BYTES);

    hop_gemv_kernel<<<3072, 256, SMEM_A_BYTES>>>(hop1, hop2, hop3, X);
    presum_kernel<<<240, 256>>>();
    mlp_kernel<<<256, 256, SMEM_MLP_BYTES>>>(X, W1, b1, W2, b2);
    segpool_kernel<<<NB_SEG, 128>>>(bidx, out);
}

// round 17
// speedup vs baseline: 1.0062x; 1.0035x over previous
#include <cuda_runtime.h>
#include <cstdint>
#include <cstddef>

#define NN 8192
#define RWD 10
#define HD1 100
#define HD2 100
#define NB_SEG 256
#define NCHUNK 8

#define MSPLIT 16
#define MW 64                       // m-window per stage
#define ROWSB 128                   // rows per block (32 lanes x 4)
#define ITERS ((NN / MSPLIT) / MW)  // 8
#define HOP_TILE_BYTES (ROWSB * MW * 4)   // 32768
#define X_TILE_BYTES (MW * RWD * 4)       // 2560
// triple-buffered: depth-2 prefetch (proven best R8/R10/R12)
#define SMEM_A_BYTES (3 * (HOP_TILE_BYTES + X_TILE_BYTES))  // 105984 -> 2 blocks/SM

typedef unsigned long long u64;

// ---------------- scratch (static device arrays; no allocation) ----------------
__device__ float g_part[3 * MSPLIT * NN * RWD];  // per-m-split partials of hopX
__device__ float g_nodeout[NN * HD2];            // per-node summed MLP output
__device__ float g_segpart[NCHUNK * NB_SEG * HD2]; // per-chunk segment partials

// ---------------- helpers ----------------
__device__ __forceinline__ void fma2(u64 &acc, u64 a, u64 b) {
    asm("fma.rn.f32x2 %0, %1, %2, %0;" : "+l"(acc) : "l"(a), "l"(b));
}
__device__ __forceinline__ u64 pack2(float x, float y) {
    u64 r; asm("mov.b64 %0, {%1, %2};" : "=l"(r) : "f"(x), "f"(y)); return r;
}
__device__ __forceinline__ float2 unpack2(u64 v) {
    float2 r; asm("mov.b64 {%0, %1}, %2;" : "=f"(r.x), "=f"(r.y) : "l"(v)); return r;
}
__device__ __forceinline__ void cp_async16(uint32_t dst, const void* src) {
    asm volatile("cp.async.cg.shared.global [%0], [%1], 16;" :: "r"(dst), "l"(src));
}
__device__ __forceinline__ void cp_commit() { asm volatile("cp.async.commit_group;"); }
template<int N> __device__ __forceinline__ void cp_wait() {
    asm volatile("cp.async.wait_group %0;" :: "n"(N));
}

// =====================================================================
// Kernel A: partial hopX over this block's m-range (512 m of one hop).
// Exact R12 configuration (best measured: 126.6us, 82% DRAM).
// =====================================================================
extern "C" __global__ void __launch_bounds__(256, 2)
hop_gemv_kernel(const float* __restrict__ hop0, const float* __restrict__ hop1,
                const float* __restrict__ hop2, const float* __restrict__ X)
{
    extern __shared__ char smem[];
    char* hop_s = smem;                                   // 3 x 32KB
    char* x_s   = smem + 3 * HOP_TILE_BYTES;              // 3 x 2.5KB

    const int b   = blockIdx.x;                  // 3072 blocks
    const int k   = b >> 10;                     // 0..2
    const int rem = b & 1023;
    const int rg  = rem >> 4;                    // row group 0..63
    const int sp  = rem & 15;                    // m split 0..15
    const int row0   = rg * ROWSB;
    const int m_base = sp * (NN / MSPLIT);
    const float* hop = (k == 0) ? hop0 : (k == 1) ? hop1 : hop2;

    const int t = threadIdx.x;
    const int w = t >> 5, l = t & 31;

    const int tr = t >> 4;                    // 0..15
    const int tc = t & 15;                    // float4 column 0..15
    const int slotS = tc ^ (tr & 7);
    const char* gsrc0 = (const char*)(hop + (size_t)(row0 + tr) * NN + m_base + tc * 4);
    const uint32_t hdst0 = (uint32_t)__cvta_generic_to_shared(hop_s)
                         + (uint32_t)((tr * 16 + slotS) * 16);
    const char* xsrc0 = (const char*)(X + (size_t)m_base * RWD);
    const uint32_t xdst0 = (uint32_t)__cvta_generic_to_shared(x_s) + (uint32_t)(t * 16);

    auto stage = [&](int buf, int it) {
        const char* gs = gsrc0 + (size_t)it * (MW * 4);
        uint32_t hd = hdst0 + buf * HOP_TILE_BYTES;
        #pragma unroll
        for (int i = 0; i < 8; i++)
            cp_async16(hd + i * 4096, gs + (size_t)i * (16 * NN * 4));
        if (t < 160)
            cp_async16(xdst0 + buf * X_TILE_BYTES, xsrc0 + (size_t)it * X_TILE_BYTES + t * 16);
        cp_commit();
    };

    u64 acc[4][5];
    #pragma unroll
    for (int g = 0; g < 4; g++)
        #pragma unroll
        for (int p = 0; p < 5; p++) acc[g][p] = 0ull;

    stage(0, 0);
    stage(1, 1);

    int bc = 2;
    #pragma unroll 1
    for (int it = 0; it < ITERS; it++) {
        __syncthreads();                    // compute(it-1) done -> buffer free
        if (it + 2 < ITERS) {
            stage(bc, it + 2);
            bc = (bc == 2) ? 0 : bc + 1;
            cp_wait<2>();
        } else if (it + 1 < ITERS) cp_wait<1>();
        else                       cp_wait<0>();
        __syncthreads();                    // buffer it visible to all warps

        const float4* hb = (const float4*)(hop_s + (it % 3) * HOP_TILE_BYTES);
        const u64*    xb = (const u64*)(x_s + (it % 3) * X_TILE_BYTES);

        #pragma unroll
        for (int q = 0; q < 2; q++) {
            const int c4   = (w << 1) + q;          // 0..15
            const int slot = c4 ^ (l & 7);
            float4 h4[4];
            #pragma unroll
            for (int g = 0; g < 4; g++)
                h4[g] = hb[((l + (g << 5)) << 4) + slot];
            const u64* xp = xb + c4 * 20;
            #pragma unroll
            for (int j = 0; j < 4; j++) {
                const float* hv0 = (const float*)&h4[0];
                const float* hv1 = (const float*)&h4[1];
                const float* hv2 = (const float*)&h4[2];
                const float* hv3 = (const float*)&h4[3];
                u64 A0 = pack2(hv0[j], hv0[j]);
                u64 A1 = pack2(hv1[j], hv1[j]);
                u64 A2 = pack2(hv2[j], hv2[j]);
                u64 A3 = pack2(hv3[j], hv3[j]);
                #pragma unroll
                for (int p = 0; p < 5; p++) {
                    u64 xv = xp[j * 5 + p];
                    fma2(acc[0][p], A0, xv);
                    fma2(acc[1][p], A1, xv);
                    fma2(acc[2][p], A2, xv);
                    fma2(acc[3][p], A3, xv);
                }
            }
        }
    }

    float* red = (float*)smem;
    __syncthreads();
    #pragma unroll
    for (int g = 0; g < 4; g++) {
        int row = l + (g << 5);
        #pragma unroll
        for (int p = 0; p < 5; p++) {
            float2 v = unpack2(acc[g][p]);
            red[(w * ROWSB + row) * RWD + 2 * p]     = v.x;
            red[(w * ROWSB + row) * RWD + 2 * p + 1] = v.y;
        }
    }
    __syncthreads();
    for (int f = t; f < ROWSB * RWD; f += 256) {
        int row = f / RWD, d = f % RWD;
        float s = 0.f;
        #pragma unroll
        for (int ww = 0; ww < 8; ww++) s += red[(ww * ROWSB + row) * RWD + d];
        g_part[((size_t)(k * MSPLIT + sp) * NN + row0 + row) * RWD + d] = s;
    }
}

// =====================================================================
// Kernel B: node-parallel MLP, 256 blocks x 32 nodes. (exact R12 version)
// =====================================================================
#define W2S_BYTES 40000
#define SMEM_H_OFF   80000            // hsm: [32][100] float = 12800B
#define SMEM_INP_OFF 92800            // inp: 1280B
#define SMEM_B2_OFF  94080            // b2s: 400B
#define SMEM_MLP_BYTES 94592

extern "C" __global__ void __launch_bounds__(256, 2)
mlp_kernel(const float* __restrict__ X, const float* __restrict__ W1,
           const float* __restrict__ b1, const float* __restrict__ W2,
           const float* __restrict__ b2)
{
    extern __shared__ char smemb[];
    float* hsm  = (float*)(smemb + SMEM_H_OFF);   // [32][100] h (plain)
    float* inp  = (float*)(smemb + SMEM_INP_OFF); // [320]
    float* b2s  = (float*)(smemb + SMEM_B2_OFF);  // [100]

    const int t = threadIdx.x;
    const int w = t >> 5, l = t & 31;
    const int node0 = blockIdx.x * 32;

    const uint32_t w2base = (uint32_t)__cvta_generic_to_shared(smemb);

    auto stageW2 = [&](int buf, int k) {
        const float4* src = (const float4*)(W2 + k * 10000);  // 2500 x 16B
        uint32_t dst = w2base + buf * W2S_BYTES;
        #pragma unroll
        for (int i = 0; i < 9; i++)
            cp_async16(dst + (i * 256 + t) * 16, src + i * 256 + t);
        if (t < 196)
            cp_async16(dst + (2304 + t) * 16, src + 2304 + t);
        cp_commit();
    };

    if (t < 100) b2s[t] = b2[t] + b2[100 + t] + b2[200 + t] + b2[300 + t];

    stageW2(0, 0);
    stageW2(1, 1);

    u64 acc[8][2];
    #pragma unroll
    for (int nn = 0; nn < 8; nn++) { acc[nn][0] = 0ull; acc[nn][1] = 0ull; }

    #pragma unroll 1
    for (int k = 0; k < 4; k++) {
        if (k == 0) {
            for (int f = t; f < 320; f += 256) inp[f] = X[(size_t)node0 * RWD + f];
        } else {
            const float* base = g_part + ((size_t)(k - 1) * MSPLIT * NN + node0) * RWD;
            for (int f = t; f < 320; f += 256) {
                float s = 0.f;
                #pragma unroll
                for (int sp = 0; sp < MSPLIT; sp++)
                    s += base[(size_t)sp * NN * RWD + f];
                inp[f] = s;
            }
        }
        if (k < 3) cp_wait<1>(); else cp_wait<0>();
        __syncthreads();   // weights(k) + inp visible; hsm free

        // ---- phase 1: warp = 4 nodes, lane<25 = j-quad ----
        if (l < 25) {
            const float* w1k = W1 + k * 1000;
            ulonglong2 w1p[10];
            #pragma unroll
            for (int r = 0; r < 10; r++)
                w1p[r] = *(const ulonglong2*)(w1k + r * 100 + 4 * l);
            float4 b1q = *(const float4*)(b1 + k * 100 + 4 * l);
            u64 binit0 = pack2(b1q.x, b1q.y), binit1 = pack2(b1q.z, b1q.w);
            #pragma unroll
            for (int nn = 0; nn < 4; nn++) {
                const int row = w * 4 + nn;
                u64 s0 = binit0, s1 = binit1;
                #pragma unroll
                for (int r = 0; r < 10; r++) {
                    float xv = inp[row * 10 + r];   // broadcast
                    u64 xp2 = pack2(xv, xv);
                    fma2(s0, xp2, w1p[r].x);
                    fma2(s1, xp2, w1p[r].y);
                }
                float2 a = unpack2(s0), bvv = unpack2(s1);
                float4 hq = { fmaxf(a.x, 0.f), fmaxf(a.y, 0.f),
                              fmaxf(bvv.x, 0.f), fmaxf(bvv.y, 0.f) };
                *(float4*)&hsm[row * 100 + 4 * l] = hq;   // plain, 16B
            }
        }
        __syncthreads();

        // ---- phase 2: warps 0-3, 8 nodes each; lane<25 = o-quad ----
        if (w < 4 && l < 25) {
            const float* w2f = (const float*)(smemb + (k & 1) * W2S_BYTES);
            #pragma unroll 5
            for (int d4 = 0; d4 < 25; d4++) {
                u64 wq[4][2];
                #pragma unroll
                for (int j = 0; j < 4; j++) {
                    ulonglong2 ww = *(const ulonglong2*)&w2f[(4 * d4 + j) * 100 + 4 * l];
                    wq[j][0] = ww.x; wq[j][1] = ww.y;
                }
                #pragma unroll
                for (int nn = 0; nn < 8; nn++) {
                    const int row = w * 8 + nn;
                    float4 hq = *(const float4*)&hsm[row * 100 + 4 * d4];  // broadcast
                    u64 h0 = pack2(hq.x, hq.x);
                    u64 h1 = pack2(hq.y, hq.y);
                    u64 h2 = pack2(hq.z, hq.z);
                    u64 h3 = pack2(hq.w, hq.w);
                    fma2(acc[nn][0], h0, wq[0][0]); fma2(acc[nn][1], h0, wq[0][1]);
                    fma2(acc[nn][0], h1, wq[1][0]); fma2(acc[nn][1], h1, wq[1][1]);
                    fma2(acc[nn][0], h2, wq[2][0]); fma2(acc[nn][1], h2, wq[2][1]);
                    fma2(acc[nn][0], h3, wq[3][0]); fma2(acc[nn][1], h3, wq[3][1]);
                }
            }
        }
        __syncthreads();   // w2 buffer (k&1) free for restage
        if (k + 2 < 4) stageW2(k & 1, k + 2);
    }

    // ---- output: node_out = acc + sum_k b2 ----
    if (w < 4 && l < 25) {
        float4 bv = *(const float4*)&b2s[4 * l];
        #pragma unroll
        for (int nn = 0; nn < 8; nn++) {
            int n = node0 + w * 8 + nn;
            float2 a0 = unpack2(acc[nn][0]);
            float2 a1 = unpack2(acc[nn][1]);
            float4 o4 = { a0.x + bv.x, a0.y + bv.y, a1.x + bv.z, a1.y + bv.w };
            *(float4*)&g_nodeout[(size_t)n * 100 + 4 * l] = o4;
        }
    }
}

// =====================================================================
// Kernel C1: segment partial sums, 256 segments x 8 node-chunks (2048
// blocks). Chunk c covers nodes lo+c, lo+c+8, ... (fixed map, fixed order
// -> deterministic). ~4 loads/thread; latency overlapped across blocks.
// =====================================================================
__device__ __forceinline__ int lbound(const int* a, int n, int v) {
    int lo = 0, hi = n;
    while (lo < hi) { int mid = (lo + hi) >> 1; if (a[mid] < v) lo = mid + 1; else hi = mid; }
    return lo;
}

extern "C" __global__ void segpool1_kernel(const int* __restrict__ bidx)
{
    const int b = blockIdx.x;              // segment
    const int c = blockIdx.y;              // chunk
    const int lo = lbound(bidx, NN, b);
    const int hi = lbound(bidx, NN, b + 1);
    const int t = threadIdx.x;
    if (t < 100) {
        float s = 0.f;
        for (int n = lo + c; n < hi; n += NCHUNK)
            s += g_nodeout[(size_t)n * 100 + t];
        g_segpart[(c * NB_SEG + b) * HD2 + t] = s;
    }
}

// =====================================================================
// Kernel C2: combine the 8 chunk partials (fixed order) + segment-count
// times summed b2 is NOT needed here (b2 already added per node).
// =====================================================================
extern "C" __global__ void segpool2_kernel(float* __restrict__ out)
{
    const int b = blockIdx.x;
    const int t = threadIdx.x;
    if (t < 100) {
        float s = 0.f;
        #pragma unroll
        for (int c = 0; c < NCHUNK; c++)
            s += g_segpart[(c * NB_SEG + b) * HD2 + t];
        out[b * 100 + t] = s;
    }
}

// =====================================================================
extern "C" void kernel_launch(void* const* d_in, const int* in_sizes, int n_in,
                              void* d_out, int out_size)
{
    const float* X    = (const float*)d_in[0];   // walk_feats (8192,10)
    const float* hop1 = (const float*)d_in[1];
    const float* hop2 = (const float*)d_in[2];
    const float* hop3 = (const float*)d_in[3];
    const int*   bidx = (const int*)d_in[4];
    const float* W1   = (const float*)d_in[5];   // (4,10,100)
    const float* b1   = (const float*)d_in[6];   // (4,100)
    const float* W2   = (const float*)d_in[7];   // (4,100,100)
    const float* b2   = (const float*)d_in[8];   // (4,100)
    float* out = (float*)d_out;                  // (256,100)

    (void)in_sizes; (void)n_in; (void)out_size;

    cudaFuncSetAttribute(hop_gemv_kernel, cudaFuncAttributeMaxDynamicSharedMemorySize, SMEM_A_BYTES);
    cudaFuncSetAttribute(mlp_kernel,      cudaFuncAttributeMaxDynamicSharedMemorySize, SMEM_MLP_BYTES);

    hop_gemv_kernel<<<3072, 256, SMEM_A_BYTES>>>(hop1, hop2, hop3, X);
    mlp_kernel<<<256, 256, SMEM_MLP_BYTES>>>(X, W1, b1, W2, b2);
    segpool1_kernel<<<dim3(NB_SEG, NCHUNK), 128>>>(bidx);
    segpool2_kernel<<<NB_SEG, 128>>>(out);
}